// round 14
// baseline (speedup 1.0000x reference)
#include <cuda_runtime.h>

// Problem constants
#define NQPTS 4096
#define HID   1024
#define RR    4096   // R*K = R*R = 64*64
#define NPTS  16384
#define SUBS  64     // k1 sub-blocks per MLP (64 points each)
#define NHC   8      // k2 h-chunks (128 rows each)

// ---------------- scratch (device globals; no allocation allowed) ----------
__device__ __align__(16)  float g_partT[2][HID][SUBS]; // transposed partial t
__device__ __align__(128) float g_ysum[2][SUBS];       // per-task partial y-sums
__device__ __align__(16)  float g_Spart[2][NHC][RR];   // h-chunked partial S
__device__ __align__(16)  float g_r[RR];               // rhs flattened [64*64]
__device__ __align__(128) float g_v[HID];              // Wx2 @ r
__device__ __align__(128) float g_cpart[16];           // partial bx2 . r
__device__ __align__(128) float g_c;                   // bx2 . r

__device__ __forceinline__ float tanh_fast(float x) {
    float y;
    asm("tanh.approx.f32 %0, %1;" : "=f"(y) : "f"(x));
    return y;
}

// Forced-order loads: volatile asm pins issue order -> guaranteed deep MLP.
__device__ __forceinline__ float4 ldg4(const float4* p) {
    float4 v;
    asm volatile("ld.global.nc.v4.f32 {%0,%1,%2,%3}, [%4];"
                 : "=f"(v.x), "=f"(v.y), "=f"(v.z), "=f"(v.w) : "l"(p));
    return v;
}
__device__ __forceinline__ float ldgf(const float* p) {
    float v;
    asm volatile("ld.global.nc.f32 %0, [%1];" : "=f"(v) : "l"(p));
    return v;
}
__device__ __forceinline__ float ldcg(const float* p) {
    float v;
    asm volatile("ld.global.cg.f32 %0, [%1];" : "=f"(v) : "l"(p));
    return v;
}

// ---------------------------------------------------------------------------
// K1: per quad point i: y_i = exp(-eq*||x||^2); accumulate
//     t[h] += y_i * tanh(x_i . W[:,h] + b[h]); store TRANSPOSED partials.
// grid: 128 blocks (2 MLPs x 64 sub-blocks of 64 points), 256 threads.
// ---------------------------------------------------------------------------
__global__ void __launch_bounds__(256)
k1_quad(const float* __restrict__ qx0, const float* __restrict__ qx1,
        const float* __restrict__ Wq0a, const float* __restrict__ bq0a,
        const float* __restrict__ Wq1a, const float* __restrict__ bq1a,
        const float* __restrict__ eq)
{
    const int blk = blockIdx.x;
    const int mlp = blk >> 6;
    const int sub = blk & (SUBS - 1);
    const float* __restrict__ qx = mlp ? qx1 : qx0;
    const float* __restrict__ W  = mlp ? Wq1a : Wq0a;
    const float* __restrict__ B  = mlp ? bq1a : bq0a;
    const int base = sub * 64;
    const int tid = threadIdx.x;

    __shared__ float sx0[64], sx1[64], sx2[64], sy[64];
    if (tid < 64) {
        float x0 = qx[(base + tid) * 3 + 0];
        float x1 = qx[(base + tid) * 3 + 1];
        float x2 = qx[(base + tid) * 3 + 2];
        sx0[tid] = x0; sx1[tid] = x1; sx2[tid] = x2;
        sy[tid]  = __expf(-ldgf(eq) * (x0 * x0 + x1 * x1 + x2 * x2));
    }
    __syncthreads();

    float w0[4], w1[4], w2[4], bb[4], acc[4];
#pragma unroll
    for (int k = 0; k < 4; k++) {
        int h = tid + 256 * k;
        w0[k] = ldgf(W + h);
        w1[k] = ldgf(W + HID + h);
        w2[k] = ldgf(W + 2 * HID + h);
        bb[k] = ldgf(B + h);
        acc[k] = 0.0f;
    }
#pragma unroll 4
    for (int p = 0; p < 64; p++) {
        float x0 = sx0[p], x1 = sx1[p], x2 = sx2[p], y = sy[p];
#pragma unroll
        for (int k = 0; k < 4; k++) {
            float a = fmaf(x0, w0[k], fmaf(x1, w1[k], fmaf(x2, w2[k], bb[k])));
            acc[k] = fmaf(y, tanh_fast(a), acc[k]);
        }
    }
#pragma unroll
    for (int k = 0; k < 4; k++)
        g_partT[mlp][tid + 256 * k][sub] = acc[k];   // transposed scatter-store
    if (tid == 0) {
        float s = 0.0f;
#pragma unroll
        for (int p = 0; p < 64; p++) s += sy[p];
        g_ysum[mlp][sub] = s;
    }
    cudaTriggerProgrammaticLaunchCompletion();
}

// ---------------------------------------------------------------------------
// K2: Spart[hc][j] = sum_{h in 128-row chunk} t[h]*Wqb[h,j] (+ ys*bqb hc==0)
// grid: 256 blocks (2 MLPs x 8 h-chunks x 16 j-chunks of 256 cols), 256 thr.
// t-phase: ONE forced 16-deep float4 batch per h (transposed partials).
// W stream: thread owns f4 col (tid&63) + row-quarter (tid>>6), 4x8-deep.
// ---------------------------------------------------------------------------
__global__ void __launch_bounds__(256)
k2_S(const float* __restrict__ Wq0b, const float* __restrict__ bq0b,
     const float* __restrict__ Wq1b, const float* __restrict__ bq1b)
{
    cudaGridDependencySynchronize();

    const int blk = blockIdx.x;       // 0..255
    const int mlp = blk >> 7;
    const int rest = blk & 127;
    const int hc = rest >> 4;         // 0..7 (128 rows each)
    const int jc = rest & 15;         // 0..15 (256 cols = 64 float4)
    const float* __restrict__ W = mlp ? Wq1b : Wq0b;
    const float* __restrict__ B = mlp ? bq1b : bq0b;
    const int tid = threadIdx.x;      // 0..255
    const int hbase = hc * 128;
    const int cbase = jc * 64;        // float4 col base

    __shared__ float t[128];
    __shared__ float4 tp[4][64];
    __shared__ float sys;

    // ---- t reduction: 1 h per thread (tid<128), ONE 16-deep f4 batch -------
    if (tid < 128) {
        const float4* __restrict__ p =
            (const float4*)&g_partT[mlp][hbase + tid][0];
        float4 v[16];
#pragma unroll
        for (int u = 0; u < 16; u++) v[u] = ldg4(p + u);
        float s = 0.0f;
#pragma unroll
        for (int u = 0; u < 16; u++)
            s += (v[u].x + v[u].y) + (v[u].z + v[u].w);
        t[tid] = s;
    }
    if (hc == 0 && tid >= 128 && tid < 160) {
        int l = tid - 128;
        float s = ldcg(&g_ysum[mlp][l]) + ldcg(&g_ysum[mlp][l + 32]);
#pragma unroll
        for (int o = 16; o; o >>= 1) s += __shfl_xor_sync(0xffffffffu, s, o);
        if (l == 0) sys = s;
    }
    __syncthreads();

    // ---- W stream: q-th row-quarter (32 rows), col cbase + (tid&63) --------
    const int q = tid >> 6;           // 0..3
    const int c = tid & 63;
    const float4* __restrict__ W4 =
        (const float4*)W + (size_t)(hbase + q * 32) * (RR / 4) + cbase + c;
    float4 A = make_float4(0.f, 0.f, 0.f, 0.f);
#pragma unroll
    for (int b = 0; b < 4; b++) {
        float4 w[8];
#pragma unroll
        for (int u = 0; u < 8; u++)
            w[u] = ldg4(W4 + (size_t)(b * 8 + u) * (RR / 4));
#pragma unroll
        for (int u = 0; u < 8; u++) {
            float th = t[q * 32 + b * 8 + u];
            A.x = fmaf(th, w[u].x, A.x);
            A.y = fmaf(th, w[u].y, A.y);
            A.z = fmaf(th, w[u].z, A.z);
            A.w = fmaf(th, w[u].w, A.w);
        }
    }
    tp[q][c] = A;
    __syncthreads();
    if (tid < 64) {
        float4 a0 = tp[0][tid], a1 = tp[1][tid], a2 = tp[2][tid], a3 = tp[3][tid];
        float4 r = make_float4((a0.x + a1.x) + (a2.x + a3.x),
                               (a0.y + a1.y) + (a2.y + a3.y),
                               (a0.z + a1.z) + (a2.z + a3.z),
                               (a0.w + a1.w) + (a2.w + a3.w));
        if (hc == 0) {
            float ys = sys;
            float4 b4 = ldg4((const float4*)B + cbase + tid);
            r.x = fmaf(ys, b4.x, r.x); r.y = fmaf(ys, b4.y, r.y);
            r.z = fmaf(ys, b4.z, r.z); r.w = fmaf(ys, b4.w, r.w);
        }
        ((float4*)&g_Spart[mlp][hc][0])[cbase + tid] = r;
    }
    cudaTriggerProgrammaticLaunchCompletion();
}

// ---------------------------------------------------------------------------
// K3: reduce 8 Spart partials (forced staging batch) -> padded smem S0/S1,
// then r[b*64+d] = sum_x S0[b,x]*S1[d,x]; per-block cpart = bx2-dot partial.
// grid: 16 blocks x 256 threads (4 b-rows per block).
// ---------------------------------------------------------------------------
__global__ void __launch_bounds__(256)
k3_rhs(const float* __restrict__ bx2)
{
    cudaGridDependencySynchronize();

    __shared__ float s1[64 * 65];
    __shared__ float s0[4 * 65];
    __shared__ float p8[8];
    const int tid = threadIdx.x;   // 0..255
    const int bbase = blockIdx.x * 4;

    const float4* __restrict__ base1 = (const float4*)g_Spart + (size_t)NHC * (RR / 4);
    const float4* __restrict__ base0 = (const float4*)g_Spart;

    // forced batches: S1 = 4 cols x 8 partials; S0 = 8 partials (tid<64)
    float4 vv[32];
#pragma unroll
    for (int k = 0; k < 4; k++)
#pragma unroll
        for (int p = 0; p < 8; p++)
            vv[k * 8 + p] = ldg4(base1 + (size_t)p * (RR / 4) + k * 256 + tid);
    float4 w0 = make_float4(0.f, 0.f, 0.f, 0.f);
    if (tid < 64) {
        float4 u[8];
#pragma unroll
        for (int p = 0; p < 8; p++)
            u[p] = ldg4(base0 + (size_t)p * (RR / 4) + bbase * 16 + tid);
#pragma unroll
        for (int p = 0; p < 8; p++) {
            w0.x += u[p].x; w0.y += u[p].y; w0.z += u[p].z; w0.w += u[p].w;
        }
    }

#pragma unroll
    for (int k = 0; k < 4; k++) {
        float4 a = make_float4(0.f, 0.f, 0.f, 0.f);
#pragma unroll
        for (int p = 0; p < 8; p++) {
            a.x += vv[k * 8 + p].x; a.y += vv[k * 8 + p].y;
            a.z += vv[k * 8 + p].z; a.w += vv[k * 8 + p].w;
        }
        int j4 = k * 256 + tid;
        float* dst = s1 + (j4 >> 4) * 65 + (j4 & 15) * 4;
        dst[0] = a.x; dst[1] = a.y; dst[2] = a.z; dst[3] = a.w;
    }
    if (tid < 64) {
        float* dst = s0 + (tid >> 4) * 65 + (tid & 15) * 4;
        dst[0] = w0.x; dst[1] = w0.y; dst[2] = w0.z; dst[3] = w0.w;
    }
    __syncthreads();

    const int b = tid >> 6;        // 0..3
    const int d = tid & 63;
    float acc = 0.0f;
#pragma unroll 16
    for (int x = 0; x < 64; x++)
        acc = fmaf(s0[b * 65 + x], s1[d * 65 + x], acc);
    const int o = (bbase + b) * 64 + d;
    g_r[o] = acc;

    float cacc = acc * ldgf(bx2 + o);
#pragma unroll
    for (int o2 = 16; o2; o2 >>= 1) cacc += __shfl_xor_sync(0xffffffffu, cacc, o2);
    if ((tid & 31) == 0) p8[tid >> 5] = cacc;
    __syncthreads();
    if (tid == 0) {
        float s = 0.0f;
#pragma unroll
        for (int i = 0; i < 8; i++) s += p8[i];
        g_cpart[blockIdx.x] = s;
    }
    cudaTriggerProgrammaticLaunchCompletion();
}

// ---------------------------------------------------------------------------
// K4: v[h] = Wx2[h,:] . r.  256 blocks x 256 threads, 4 rows per block;
// 64 threads per row, 16-deep forced W batch preloaded BEFORE the dependency
// sync (overlaps k3's drain), 16-deep r batch (L2) after. Block 0 finalizes c.
// ---------------------------------------------------------------------------
__global__ void __launch_bounds__(256)
k4_v(const float* __restrict__ Wx2)
{
    const int tid = threadIdx.x;
    const int row = tid >> 6;                      // 0..3
    const int h = blockIdx.x * 4 + row;
    const int g = tid & 63;
    const float4* __restrict__ W4 = (const float4*)Wx2 + (size_t)h * (RR / 4) + g;

    float4 w[16];
#pragma unroll
    for (int k = 0; k < 16; k++)
        w[k] = ldg4(W4 + 64 * k);        // independent prologue (DRAM)

    cudaGridDependencySynchronize();

    if (blockIdx.x == 0 && tid == 0) {
        float s = 0.0f;
#pragma unroll
        for (int i = 0; i < 16; i++) s += ldcg(&g_cpart[i]);
        g_c = s;
    }

    float4 r[16];
#pragma unroll
    for (int k = 0; k < 16; k++)
        r[k] = ldg4((const float4*)g_r + g + 64 * k);
    float acc = 0.0f;
#pragma unroll
    for (int k = 0; k < 16; k++) {
        acc = fmaf(w[k].x, r[k].x, acc);
        acc = fmaf(w[k].y, r[k].y, acc);
        acc = fmaf(w[k].z, r[k].z, acc);
        acc = fmaf(w[k].w, r[k].w, acc);
    }
#pragma unroll
    for (int o = 16; o; o >>= 1) acc += __shfl_xor_sync(0xffffffffu, acc, o);
    __shared__ float part[8];
    if ((tid & 31) == 0) part[tid >> 5] = acc;
    __syncthreads();
    if (tid < 4)
        g_v[blockIdx.x * 4 + tid] = part[2 * tid] + part[2 * tid + 1];
    cudaTriggerProgrammaticLaunchCompletion();
}

// ---------------------------------------------------------------------------
// K5: out[n] = tanh(input[n] @ Wx1 + bx1) . v + c
// 512 blocks x 256 threads; Wx1/bx1 AND input staged BEFORE the sync.
// ---------------------------------------------------------------------------
__global__ void __launch_bounds__(256)
k5_out(const float* __restrict__ input, const float* __restrict__ Wx1,
       const float* __restrict__ bx1, float* __restrict__ out)
{
    __shared__ float4 swb[HID];   // (w0, w1, w2, bias)
    __shared__ float  sv[HID];
    const int tid = threadIdx.x;
    const int warp = tid >> 5, lane = tid & 31;
    const int nbase = (blockIdx.x * 8 + warp) * 4;

    float a0[4], a1[4], a2[4], a3[4], a4[4];
#pragma unroll
    for (int k = 0; k < 4; k++) {
        int h = tid + 256 * k;
        a0[k] = ldgf(Wx1 + h);
        a1[k] = ldgf(Wx1 + HID + h);
        a2[k] = ldgf(Wx1 + 2 * HID + h);
        a3[k] = ldgf(bx1 + h);
    }
    float x0[4], x1[4], x2[4];
#pragma unroll
    for (int nn = 0; nn < 4; nn++) {
        x0[nn] = ldgf(input + (nbase + nn) * 3 + 0);
        x1[nn] = ldgf(input + (nbase + nn) * 3 + 1);
        x2[nn] = ldgf(input + (nbase + nn) * 3 + 2);
    }

    cudaGridDependencySynchronize();

#pragma unroll
    for (int k = 0; k < 4; k++)
        a4[k] = ldcg(&g_v[tid + 256 * k]);
#pragma unroll
    for (int k = 0; k < 4; k++) {
        int h = tid + 256 * k;
        swb[h] = make_float4(a0[k], a1[k], a2[k], a3[k]);
        sv[h] = a4[k];
    }
    __syncthreads();

    const float c = ldcg(&g_c);
    float acc[4] = {0.0f, 0.0f, 0.0f, 0.0f};
#pragma unroll 4
    for (int k = 0; k < 32; k++) {
        int h = k * 32 + lane;
        float4 wb = swb[h];
        float vv = sv[h];
#pragma unroll
        for (int nn = 0; nn < 4; nn++) {
            float a = fmaf(x0[nn], wb.x, fmaf(x1[nn], wb.y, fmaf(x2[nn], wb.z, wb.w)));
            acc[nn] = fmaf(tanh_fast(a), vv, acc[nn]);
        }
    }
#pragma unroll
    for (int nn = 0; nn < 4; nn++) {
        float a = acc[nn];
#pragma unroll
        for (int o = 16; o; o >>= 1) a += __shfl_xor_sync(0xffffffffu, a, o);
        if (lane == 0) out[nbase + nn] = a + c;
    }
}

// ---------------------------------------------------------------------------
// Input order (metadata): 0 input, 1 eq_param, 2 quad_x0, 3 quad_x1,
// 4 Wx1, 5 bx1, 6 Wx2, 7 bx2, 8 Wq0a, 9 bq0a, 10 Wq0b, 11 bq0b,
// 12 Wq1a, 13 bq1a, 14 Wq1b, 15 bq1b
// ---------------------------------------------------------------------------
extern "C" void kernel_launch(void* const* d_in, const int* in_sizes, int n_in,
                              void* d_out, int out_size)
{
    const float* input  = (const float*)d_in[0];
    const float* eq     = (const float*)d_in[1];
    const float* qx0    = (const float*)d_in[2];
    const float* qx1    = (const float*)d_in[3];
    const float* Wx1    = (const float*)d_in[4];
    const float* bx1    = (const float*)d_in[5];
    const float* Wx2    = (const float*)d_in[6];
    const float* bx2    = (const float*)d_in[7];
    const float* Wq0a   = (const float*)d_in[8];
    const float* bq0a   = (const float*)d_in[9];
    const float* Wq0b   = (const float*)d_in[10];
    const float* bq0b   = (const float*)d_in[11];
    const float* Wq1a   = (const float*)d_in[12];
    const float* bq1a   = (const float*)d_in[13];
    const float* Wq1b   = (const float*)d_in[14];
    const float* bq1b   = (const float*)d_in[15];
    float* out = (float*)d_out;

    cudaLaunchAttribute attr[1];
    attr[0].id = cudaLaunchAttributeProgrammaticStreamSerialization;
    attr[0].val.programmaticStreamSerializationAllowed = 1;
    cudaLaunchConfig_t cfg = {};
    cfg.attrs = attr;
    cfg.numAttrs = 1;
    cfg.stream = 0;

    cfg.gridDim = dim3(128); cfg.blockDim = dim3(256);
    cudaError_t e = cudaLaunchKernelEx(&cfg, k1_quad, qx0, qx1, Wq0a, bq0a, Wq1a, bq1a, eq);
    if (e != cudaSuccess) {
        // PDL unavailable: plain serialized launches (grid-dep sync is a no-op)
        k1_quad<<<128, 256>>>(qx0, qx1, Wq0a, bq0a, Wq1a, bq1a, eq);
        k2_S<<<256, 256>>>(Wq0b, bq0b, Wq1b, bq1b);
        k3_rhs<<<16, 256>>>(bx2);
        k4_v<<<256, 256>>>(Wx2);
        k5_out<<<512, 256>>>(input, Wx1, bx1, out);
        return;
    }
    cfg.gridDim = dim3(256); cfg.blockDim = dim3(256);
    cudaLaunchKernelEx(&cfg, k2_S, Wq0b, bq0b, Wq1b, bq1b);
    cfg.gridDim = dim3(16); cfg.blockDim = dim3(256);
    cudaLaunchKernelEx(&cfg, k3_rhs, bx2);
    cfg.gridDim = dim3(256); cfg.blockDim = dim3(256);
    cudaLaunchKernelEx(&cfg, k4_v, Wx2);
    cfg.gridDim = dim3(512); cfg.blockDim = dim3(256);
    cudaLaunchKernelEx(&cfg, k5_out, input, Wx1, bx1, out);
}

// round 15
// speedup vs baseline: 1.2697x; 1.2697x over previous
#include <cuda_runtime.h>

// Problem constants
#define NQPTS 4096
#define HID   1024
#define RR    4096   // R*K = R*R = 64*64
#define NPTS  16384
#define SUBS  64     // k1 sub-blocks per MLP (64 points each)
#define NHC   4      // k2 h-chunks (256 rows each)

// ---------------- scratch (device globals; no allocation allowed) ----------
__device__ __align__(16)  float g_part[2][SUBS][HID]; // per-task partial t-sums
__device__ __align__(128) float g_ysum[2][SUBS];      // per-task partial y-sums
__device__ __align__(16)  float g_Spart[2][NHC][RR];  // h-chunked partial S
__device__ __align__(16)  float g_r[RR];              // rhs flattened [64*64]
__device__ __align__(128) float g_v[HID];             // Wx2 @ r
__device__ __align__(128) float g_cpart[16];          // partial bx2 . r
__device__ __align__(128) float g_c;                  // bx2 . r

__device__ __forceinline__ float tanh_fast(float x) {
    float y;
    asm("tanh.approx.f32 %0, %1;" : "=f"(y) : "f"(x));
    return y;
}

// Forced-order loads: volatile asm pins issue order -> guaranteed deep MLP.
__device__ __forceinline__ float4 ldg4(const float4* p) {
    float4 v;
    asm volatile("ld.global.nc.v4.f32 {%0,%1,%2,%3}, [%4];"
                 : "=f"(v.x), "=f"(v.y), "=f"(v.z), "=f"(v.w) : "l"(p));
    return v;
}
__device__ __forceinline__ float ldgf(const float* p) {
    float v;
    asm volatile("ld.global.nc.f32 %0, [%1];" : "=f"(v) : "l"(p));
    return v;
}
__device__ __forceinline__ float ldcg(const float* p) {
    float v;
    asm volatile("ld.global.cg.f32 %0, [%1];" : "=f"(v) : "l"(p));
    return v;
}

// ---------------------------------------------------------------------------
// K1: per quad point i: y_i = exp(-eq*||x||^2); accumulate
//     t[h] += y_i * tanh(x_i . W[:,h] + b[h]) into per-task partials.
// grid: 128 blocks (2 MLPs x 64 sub-blocks of 64 points), 256 threads.
// ---------------------------------------------------------------------------
__global__ void __launch_bounds__(256)
k1_quad(const float* __restrict__ qx0, const float* __restrict__ qx1,
        const float* __restrict__ Wq0a, const float* __restrict__ bq0a,
        const float* __restrict__ Wq1a, const float* __restrict__ bq1a,
        const float* __restrict__ eq)
{
    const int blk = blockIdx.x;
    const int mlp = blk >> 6;
    const int sub = blk & (SUBS - 1);
    const float* __restrict__ qx = mlp ? qx1 : qx0;
    const float* __restrict__ W  = mlp ? Wq1a : Wq0a;
    const float* __restrict__ B  = mlp ? bq1a : bq0a;
    const int base = sub * 64;
    const int tid = threadIdx.x;

    __shared__ float sx0[64], sx1[64], sx2[64], sy[64];
    if (tid < 64) {
        float x0 = qx[(base + tid) * 3 + 0];
        float x1 = qx[(base + tid) * 3 + 1];
        float x2 = qx[(base + tid) * 3 + 2];
        sx0[tid] = x0; sx1[tid] = x1; sx2[tid] = x2;
        sy[tid]  = __expf(-ldgf(eq) * (x0 * x0 + x1 * x1 + x2 * x2));
    }
    __syncthreads();

    float w0[4], w1[4], w2[4], bb[4], acc[4];
#pragma unroll
    for (int k = 0; k < 4; k++) {
        int h = tid + 256 * k;
        w0[k] = ldgf(W + h);
        w1[k] = ldgf(W + HID + h);
        w2[k] = ldgf(W + 2 * HID + h);
        bb[k] = ldgf(B + h);
        acc[k] = 0.0f;
    }
#pragma unroll 4
    for (int p = 0; p < 64; p++) {
        float x0 = sx0[p], x1 = sx1[p], x2 = sx2[p], y = sy[p];
#pragma unroll
        for (int k = 0; k < 4; k++) {
            float a = fmaf(x0, w0[k], fmaf(x1, w1[k], fmaf(x2, w2[k], bb[k])));
            acc[k] = fmaf(y, tanh_fast(a), acc[k]);
        }
    }
#pragma unroll
    for (int k = 0; k < 4; k++)
        g_part[mlp][sub][tid + 256 * k] = acc[k];
    if (tid == 0) {
        float s = 0.0f;
#pragma unroll
        for (int p = 0; p < 64; p++) s += sy[p];
        g_ysum[mlp][sub] = s;
    }
    cudaTriggerProgrammaticLaunchCompletion();
}

// ---------------------------------------------------------------------------
// K2: Spart[hc][j] = sum_{h in 256-row chunk} t[h]*Wqb[h,j] (+ ys*bqb hc==0)
// grid: 256 blocks (2 MLPs x 4 h-chunks x 32 j-chunks of 128 cols), 128 thr.
// Thread: one float4 col over 64 rows (8x8-deep forced batches);
// 4 row-quarter partials reduced in smem. Writes Spart directly.
// ---------------------------------------------------------------------------
__global__ void __launch_bounds__(128)
k2_S(const float* __restrict__ Wq0b, const float* __restrict__ bq0b,
     const float* __restrict__ Wq1b, const float* __restrict__ bq1b)
{
    cudaGridDependencySynchronize();

    const int blk = blockIdx.x;       // 0..255
    const int mlp = blk >> 7;
    const int rest = blk & 127;
    const int hc = rest >> 5;         // 0..3 (256 rows each)
    const int jc = rest & 31;         // 0..31 (128 cols = 32 float4)
    const float* __restrict__ W = mlp ? Wq1b : Wq0b;
    const float* __restrict__ B = mlp ? bq1b : bq0b;
    const int tid = threadIdx.x;      // 0..127
    const int hbase = hc * 256;
    const int cbase = jc * 32;        // float4 col base

    __shared__ float t[256];
    __shared__ float4 tp[4][32];
    __shared__ float sys;

    // ---- t reduction: 2 h per thread over 64 subs, forced 8-deep loads ----
    {
        const float* p0 = &g_part[mlp][0][hbase + tid];
        float s0 = 0.0f;
#pragma unroll
        for (int b = 0; b < 8; b++) {
            float v[8];
#pragma unroll
            for (int u = 0; u < 8; u++)
                v[u] = ldgf(p0 + (size_t)(b * 8 + u) * HID);
#pragma unroll
            for (int u = 0; u < 8; u++) s0 += v[u];
        }
        t[tid] = s0;
        const float* p1 = p0 + 128;
        float s1 = 0.0f;
#pragma unroll
        for (int b = 0; b < 8; b++) {
            float v[8];
#pragma unroll
            for (int u = 0; u < 8; u++)
                v[u] = ldgf(p1 + (size_t)(b * 8 + u) * HID);
#pragma unroll
            for (int u = 0; u < 8; u++) s1 += v[u];
        }
        t[tid + 128] = s1;
    }
    if (hc == 0 && tid < 32) {
        float s = ldcg(&g_ysum[mlp][tid]) + ldcg(&g_ysum[mlp][tid + 32]);
#pragma unroll
        for (int o = 16; o; o >>= 1) s += __shfl_xor_sync(0xffffffffu, s, o);
        if (tid == 0) sys = s;
    }
    __syncthreads();

    // ---- W stream: q-th row-quarter (64 rows), col cbase + (tid&31) ----
    const int q = tid >> 5;           // 0..3
    const int c = tid & 31;
    const float4* __restrict__ W4 =
        (const float4*)W + (size_t)(hbase + q * 64) * (RR / 4) + cbase + c;
    float4 A = make_float4(0.f, 0.f, 0.f, 0.f);
#pragma unroll
    for (int b = 0; b < 8; b++) {
        float4 w[8];
#pragma unroll
        for (int u = 0; u < 8; u++)
            w[u] = ldg4(W4 + (size_t)(b * 8 + u) * (RR / 4));
#pragma unroll
        for (int u = 0; u < 8; u++) {
            float th = t[q * 64 + b * 8 + u];
            A.x = fmaf(th, w[u].x, A.x);
            A.y = fmaf(th, w[u].y, A.y);
            A.z = fmaf(th, w[u].z, A.z);
            A.w = fmaf(th, w[u].w, A.w);
        }
    }
    tp[q][c] = A;
    __syncthreads();
    if (tid < 32) {
        float4 a0 = tp[0][tid], a1 = tp[1][tid], a2 = tp[2][tid], a3 = tp[3][tid];
        float4 r = make_float4((a0.x + a1.x) + (a2.x + a3.x),
                               (a0.y + a1.y) + (a2.y + a3.y),
                               (a0.z + a1.z) + (a2.z + a3.z),
                               (a0.w + a1.w) + (a2.w + a3.w));
        if (hc == 0) {
            float ys = sys;
            float4 b4 = ldg4((const float4*)B + cbase + tid);
            r.x = fmaf(ys, b4.x, r.x); r.y = fmaf(ys, b4.y, r.y);
            r.z = fmaf(ys, b4.z, r.z); r.w = fmaf(ys, b4.w, r.w);
        }
        ((float4*)&g_Spart[mlp][hc][0])[cbase + tid] = r;
    }
    cudaTriggerProgrammaticLaunchCompletion();
}

// ---------------------------------------------------------------------------
// K3: reduce 4 Spart partials (in the staging batch) -> padded smem S0/S1,
// then r[b*64+d] = sum_x S0[b,x]*S1[d,x]; per-block cpart = bx2-dot partial.
// grid: 16 blocks x 256 threads (4 b-rows per block).
// ---------------------------------------------------------------------------
__global__ void __launch_bounds__(256)
k3_rhs(const float* __restrict__ bx2)
{
    cudaGridDependencySynchronize();

    __shared__ float s1[64 * 65];
    __shared__ float s0[4 * 65];
    __shared__ float p8[8];
    const int tid = threadIdx.x;   // 0..255
    const int bbase = blockIdx.x * 4;

    // one forced batch: 16 loads (S1: 4 cols x 4 partials) + 4 (S0 rows)
    const float4* __restrict__ base1 = (const float4*)g_Spart + (size_t)NHC * (RR / 4);
    const float4* __restrict__ base0 = (const float4*)g_Spart;
    float4 vv[16];
#pragma unroll
    for (int k = 0; k < 4; k++)
#pragma unroll
        for (int p = 0; p < 4; p++)
            vv[k * 4 + p] = ldg4(base1 + (size_t)p * (RR / 4) + k * 256 + tid);
    float4 w0 = make_float4(0.f, 0.f, 0.f, 0.f);
    if (tid < 64) {
        float4 u[4];
#pragma unroll
        for (int p = 0; p < 4; p++)
            u[p] = ldg4(base0 + (size_t)p * (RR / 4) + bbase * 16 + tid);
        w0.x = (u[0].x + u[1].x) + (u[2].x + u[3].x);
        w0.y = (u[0].y + u[1].y) + (u[2].y + u[3].y);
        w0.z = (u[0].z + u[1].z) + (u[2].z + u[3].z);
        w0.w = (u[0].w + u[1].w) + (u[2].w + u[3].w);
    }

#pragma unroll
    for (int k = 0; k < 4; k++) {
        float4 a = make_float4(
            (vv[k*4+0].x + vv[k*4+1].x) + (vv[k*4+2].x + vv[k*4+3].x),
            (vv[k*4+0].y + vv[k*4+1].y) + (vv[k*4+2].y + vv[k*4+3].y),
            (vv[k*4+0].z + vv[k*4+1].z) + (vv[k*4+2].z + vv[k*4+3].z),
            (vv[k*4+0].w + vv[k*4+1].w) + (vv[k*4+2].w + vv[k*4+3].w));
        int j4 = k * 256 + tid;
        float* dst = s1 + (j4 >> 4) * 65 + (j4 & 15) * 4;
        dst[0] = a.x; dst[1] = a.y; dst[2] = a.z; dst[3] = a.w;
    }
    if (tid < 64) {
        float* dst = s0 + (tid >> 4) * 65 + (tid & 15) * 4;
        dst[0] = w0.x; dst[1] = w0.y; dst[2] = w0.z; dst[3] = w0.w;
    }
    __syncthreads();

    const int b = tid >> 6;        // 0..3
    const int d = tid & 63;
    float acc = 0.0f;
#pragma unroll 16
    for (int x = 0; x < 64; x++)
        acc = fmaf(s0[b * 65 + x], s1[d * 65 + x], acc);
    const int o = (bbase + b) * 64 + d;
    g_r[o] = acc;

    float cacc = acc * ldgf(bx2 + o);
#pragma unroll
    for (int o2 = 16; o2; o2 >>= 1) cacc += __shfl_xor_sync(0xffffffffu, cacc, o2);
    if ((tid & 31) == 0) p8[tid >> 5] = cacc;
    __syncthreads();
    if (tid == 0) {
        float s = 0.0f;
#pragma unroll
        for (int i = 0; i < 8; i++) s += p8[i];
        g_cpart[blockIdx.x] = s;
    }
    cudaTriggerProgrammaticLaunchCompletion();
}

// ---------------------------------------------------------------------------
// K4: v[h] = Wx2[h,:] . r.  512 blocks x 256 threads, 2 rows per block.
// W batch preloaded BEFORE the dependency sync (overlaps k3's drain).
// Block 0 also finalizes c = sum(cpart).
// ---------------------------------------------------------------------------
__global__ void __launch_bounds__(256)
k4_v(const float* __restrict__ Wx2)
{
    const int tid = threadIdx.x;
    const int row = tid >> 7;                      // 0 or 1
    const int h = blockIdx.x * 2 + row;
    const int g = tid & 127;
    const float4* __restrict__ W4 = (const float4*)Wx2 + (size_t)h * (RR / 4) + g;

    float4 w[8];
#pragma unroll
    for (int k = 0; k < 8; k++)
        w[k] = ldg4(W4 + 128 * k);       // independent prologue (DRAM)

    cudaGridDependencySynchronize();

    if (blockIdx.x == 0 && tid == 0) {
        float s = 0.0f;
#pragma unroll
        for (int i = 0; i < 16; i++) s += ldcg(&g_cpart[i]);
        g_c = s;
    }

    float4 r[8];
#pragma unroll
    for (int k = 0; k < 8; k++)
        r[k] = ldg4((const float4*)g_r + g + 128 * k);
    float acc = 0.0f;
#pragma unroll
    for (int k = 0; k < 8; k++) {
        acc = fmaf(w[k].x, r[k].x, acc);
        acc = fmaf(w[k].y, r[k].y, acc);
        acc = fmaf(w[k].z, r[k].z, acc);
        acc = fmaf(w[k].w, r[k].w, acc);
    }
#pragma unroll
    for (int o = 16; o; o >>= 1) acc += __shfl_xor_sync(0xffffffffu, acc, o);
    __shared__ float part[8];
    if ((tid & 31) == 0) part[tid >> 5] = acc;
    __syncthreads();
    if (tid < 2)
        g_v[blockIdx.x * 2 + tid] = (part[4 * tid] + part[4 * tid + 1]) +
                                    (part[4 * tid + 2] + part[4 * tid + 3]);
    cudaTriggerProgrammaticLaunchCompletion();
}

// ---------------------------------------------------------------------------
// K5: out[n] = tanh(input[n] @ Wx1 + bx1) . v + c
// 512 blocks x 256 threads; Wx1/bx1 AND input staged BEFORE the sync.
// ---------------------------------------------------------------------------
__global__ void __launch_bounds__(256)
k5_out(const float* __restrict__ input, const float* __restrict__ Wx1,
       const float* __restrict__ bx1, float* __restrict__ out)
{
    __shared__ float4 swb[HID];   // (w0, w1, w2, bias)
    __shared__ float  sv[HID];
    const int tid = threadIdx.x;
    const int warp = tid >> 5, lane = tid & 31;
    const int nbase = (blockIdx.x * 8 + warp) * 4;

    float a0[4], a1[4], a2[4], a3[4], a4[4];
#pragma unroll
    for (int k = 0; k < 4; k++) {
        int h = tid + 256 * k;
        a0[k] = ldgf(Wx1 + h);
        a1[k] = ldgf(Wx1 + HID + h);
        a2[k] = ldgf(Wx1 + 2 * HID + h);
        a3[k] = ldgf(bx1 + h);
    }
    float x0[4], x1[4], x2[4];
#pragma unroll
    for (int nn = 0; nn < 4; nn++) {
        x0[nn] = ldgf(input + (nbase + nn) * 3 + 0);
        x1[nn] = ldgf(input + (nbase + nn) * 3 + 1);
        x2[nn] = ldgf(input + (nbase + nn) * 3 + 2);
    }

    cudaGridDependencySynchronize();

#pragma unroll
    for (int k = 0; k < 4; k++)
        a4[k] = ldcg(&g_v[tid + 256 * k]);
#pragma unroll
    for (int k = 0; k < 4; k++) {
        int h = tid + 256 * k;
        swb[h] = make_float4(a0[k], a1[k], a2[k], a3[k]);
        sv[h] = a4[k];
    }
    __syncthreads();

    const float c = ldcg(&g_c);
    float acc[4] = {0.0f, 0.0f, 0.0f, 0.0f};
#pragma unroll 4
    for (int k = 0; k < 32; k++) {
        int h = k * 32 + lane;
        float4 wb = swb[h];
        float vv = sv[h];
#pragma unroll
        for (int nn = 0; nn < 4; nn++) {
            float a = fmaf(x0[nn], wb.x, fmaf(x1[nn], wb.y, fmaf(x2[nn], wb.z, wb.w)));
            acc[nn] = fmaf(tanh_fast(a), vv, acc[nn]);
        }
    }
#pragma unroll
    for (int nn = 0; nn < 4; nn++) {
        float a = acc[nn];
#pragma unroll
        for (int o = 16; o; o >>= 1) a += __shfl_xor_sync(0xffffffffu, a, o);
        if (lane == 0) out[nbase + nn] = a + c;
    }
}

// ---------------------------------------------------------------------------
// Input order (metadata): 0 input, 1 eq_param, 2 quad_x0, 3 quad_x1,
// 4 Wx1, 5 bx1, 6 Wx2, 7 bx2, 8 Wq0a, 9 bq0a, 10 Wq0b, 11 bq0b,
// 12 Wq1a, 13 bq1a, 14 Wq1b, 15 bq1b
// ---------------------------------------------------------------------------
extern "C" void kernel_launch(void* const* d_in, const int* in_sizes, int n_in,
                              void* d_out, int out_size)
{
    const float* input  = (const float*)d_in[0];
    const float* eq     = (const float*)d_in[1];
    const float* qx0    = (const float*)d_in[2];
    const float* qx1    = (const float*)d_in[3];
    const float* Wx1    = (const float*)d_in[4];
    const float* bx1    = (const float*)d_in[5];
    const float* Wx2    = (const float*)d_in[6];
    const float* bx2    = (const float*)d_in[7];
    const float* Wq0a   = (const float*)d_in[8];
    const float* bq0a   = (const float*)d_in[9];
    const float* Wq0b   = (const float*)d_in[10];
    const float* bq0b   = (const float*)d_in[11];
    const float* Wq1a   = (const float*)d_in[12];
    const float* bq1a   = (const float*)d_in[13];
    const float* Wq1b   = (const float*)d_in[14];
    const float* bq1b   = (const float*)d_in[15];
    float* out = (float*)d_out;

    cudaLaunchAttribute attr[1];
    attr[0].id = cudaLaunchAttributeProgrammaticStreamSerialization;
    attr[0].val.programmaticStreamSerializationAllowed = 1;
    cudaLaunchConfig_t cfg = {};
    cfg.attrs = attr;
    cfg.numAttrs = 1;
    cfg.stream = 0;

    cfg.gridDim = dim3(128); cfg.blockDim = dim3(256);
    cudaError_t e = cudaLaunchKernelEx(&cfg, k1_quad, qx0, qx1, Wq0a, bq0a, Wq1a, bq1a, eq);
    if (e != cudaSuccess) {
        // PDL unavailable: plain serialized launches (grid-dep sync is a no-op)
        k1_quad<<<128, 256>>>(qx0, qx1, Wq0a, bq0a, Wq1a, bq1a, eq);
        k2_S<<<256, 128>>>(Wq0b, bq0b, Wq1b, bq1b);
        k3_rhs<<<16, 256>>>(bx2);
        k4_v<<<512, 256>>>(Wx2);
        k5_out<<<512, 256>>>(input, Wx1, bx1, out);
        return;
    }
    cfg.gridDim = dim3(256); cfg.blockDim = dim3(128);
    cudaLaunchKernelEx(&cfg, k2_S, Wq0b, bq0b, Wq1b, bq1b);
    cfg.gridDim = dim3(16); cfg.blockDim = dim3(256);
    cudaLaunchKernelEx(&cfg, k3_rhs, bx2);
    cfg.gridDim = dim3(512); cfg.blockDim = dim3(256);
    cudaLaunchKernelEx(&cfg, k4_v, Wx2);
    cfg.gridDim = dim3(512); cfg.blockDim = dim3(256);
    cudaLaunchKernelEx(&cfg, k5_out, input, Wx1, bx1, out);
}

// round 16
// speedup vs baseline: 1.3851x; 1.0909x over previous
#include <cuda_runtime.h>

// Problem constants
#define NQPTS 4096
#define HID   1024
#define RR    4096   // R*K = R*R = 64*64
#define NPTS  16384
#define SUBS  64     // k1 sub-blocks per MLP (64 points each)
#define NHC   8      // k2 h-chunks (128 rows each)

// ---------------- scratch (device globals; no allocation allowed) ----------
__device__ __align__(16)  float g_part[2][SUBS][HID]; // per-task partial t-sums
__device__ __align__(128) float g_ysum[2][SUBS];      // per-task partial y-sums
__device__ __align__(16)  float g_Spart[2][NHC][RR];  // h-chunked partial S
__device__ __align__(16)  float g_r[RR];              // rhs flattened [64*64]
__device__ __align__(128) float g_v[HID];             // Wx2 @ r
__device__ __align__(128) float g_cpart[16];          // partial bx2 . r
__device__ __align__(128) float g_c;                  // bx2 . r

__device__ __forceinline__ float tanh_fast(float x) {
    float y;
    asm("tanh.approx.f32 %0, %1;" : "=f"(y) : "f"(x));
    return y;
}

// Forced-order loads: volatile asm pins issue order -> guaranteed deep MLP.
__device__ __forceinline__ float4 ldg4(const float4* p) {
    float4 v;
    asm volatile("ld.global.nc.v4.f32 {%0,%1,%2,%3}, [%4];"
                 : "=f"(v.x), "=f"(v.y), "=f"(v.z), "=f"(v.w) : "l"(p));
    return v;
}
__device__ __forceinline__ float ldgf(const float* p) {
    float v;
    asm volatile("ld.global.nc.f32 %0, [%1];" : "=f"(v) : "l"(p));
    return v;
}
__device__ __forceinline__ float ldcg(const float* p) {
    float v;
    asm volatile("ld.global.cg.f32 %0, [%1];" : "=f"(v) : "l"(p));
    return v;
}

// ---------------------------------------------------------------------------
// K1: per quad point i: y_i = exp(-eq*||x||^2); accumulate
//     t[h] += y_i * tanh(x_i . W[:,h] + b[h]) into per-task partials.
// grid: 128 blocks (2 MLPs x 64 sub-blocks of 64 points), 256 threads.
// ---------------------------------------------------------------------------
__global__ void __launch_bounds__(256)
k1_quad(const float* __restrict__ qx0, const float* __restrict__ qx1,
        const float* __restrict__ Wq0a, const float* __restrict__ bq0a,
        const float* __restrict__ Wq1a, const float* __restrict__ bq1a,
        const float* __restrict__ eq)
{
    const int blk = blockIdx.x;
    const int mlp = blk >> 6;
    const int sub = blk & (SUBS - 1);
    const float* __restrict__ qx = mlp ? qx1 : qx0;
    const float* __restrict__ W  = mlp ? Wq1a : Wq0a;
    const float* __restrict__ B  = mlp ? bq1a : bq0a;
    const int base = sub * 64;
    const int tid = threadIdx.x;

    __shared__ float sx0[64], sx1[64], sx2[64], sy[64];
    if (tid < 64) {
        float x0 = qx[(base + tid) * 3 + 0];
        float x1 = qx[(base + tid) * 3 + 1];
        float x2 = qx[(base + tid) * 3 + 2];
        sx0[tid] = x0; sx1[tid] = x1; sx2[tid] = x2;
        sy[tid]  = __expf(-ldgf(eq) * (x0 * x0 + x1 * x1 + x2 * x2));
    }
    __syncthreads();

    float w0[4], w1[4], w2[4], bb[4], acc[4];
#pragma unroll
    for (int k = 0; k < 4; k++) {
        int h = tid + 256 * k;
        w0[k] = ldgf(W + h);
        w1[k] = ldgf(W + HID + h);
        w2[k] = ldgf(W + 2 * HID + h);
        bb[k] = ldgf(B + h);
        acc[k] = 0.0f;
    }
#pragma unroll 4
    for (int p = 0; p < 64; p++) {
        float x0 = sx0[p], x1 = sx1[p], x2 = sx2[p], y = sy[p];
#pragma unroll
        for (int k = 0; k < 4; k++) {
            float a = fmaf(x0, w0[k], fmaf(x1, w1[k], fmaf(x2, w2[k], bb[k])));
            acc[k] = fmaf(y, tanh_fast(a), acc[k]);
        }
    }
#pragma unroll
    for (int k = 0; k < 4; k++)
        g_part[mlp][sub][tid + 256 * k] = acc[k];
    if (tid == 0) {
        float s = 0.0f;
#pragma unroll
        for (int p = 0; p < 64; p++) s += sy[p];
        g_ysum[mlp][sub] = s;
    }
    cudaTriggerProgrammaticLaunchCompletion();
}

// ---------------------------------------------------------------------------
// K2: Spart[hc][j] = sum_{h in 128-row chunk} t[h]*Wqb[h,j] (+ ys*bqb hc==0)
// grid: 512 blocks (2 MLPs x 8 h-chunks x 32 j-chunks of 128 cols), 128 thr.
// t-phase: one h per thread, 64 subs via 8x8-deep forced scalar loads.
// W stream: thread owns f4 col (tid&31) + 32-row quarter (tid>>5), 4x8-deep.
// ---------------------------------------------------------------------------
__global__ void __launch_bounds__(128)
k2_S(const float* __restrict__ Wq0b, const float* __restrict__ bq0b,
     const float* __restrict__ Wq1b, const float* __restrict__ bq1b)
{
    cudaGridDependencySynchronize();

    const int blk = blockIdx.x;       // 0..511
    const int mlp = blk >> 8;
    const int rest = blk & 255;
    const int hc = rest >> 5;         // 0..7 (128 rows each)
    const int jc = rest & 31;         // 0..31 (128 cols = 32 float4)
    const float* __restrict__ W = mlp ? Wq1b : Wq0b;
    const float* __restrict__ B = mlp ? bq1b : bq0b;
    const int tid = threadIdx.x;      // 0..127
    const int hbase = hc * 128;
    const int cbase = jc * 32;        // float4 col base

    __shared__ float t[128];
    __shared__ float4 tp[4][32];
    __shared__ float sys;

    // ---- t reduction: 1 h per thread over 64 subs, forced 8-deep loads ----
    {
        const float* p0 = &g_part[mlp][0][hbase + tid];
        float s0 = 0.0f;
#pragma unroll
        for (int b = 0; b < 8; b++) {
            float v[8];
#pragma unroll
            for (int u = 0; u < 8; u++)
                v[u] = ldgf(p0 + (size_t)(b * 8 + u) * HID);
#pragma unroll
            for (int u = 0; u < 8; u++) s0 += v[u];
        }
        t[tid] = s0;
    }
    if (hc == 0 && tid < 32) {
        float s = ldcg(&g_ysum[mlp][tid]) + ldcg(&g_ysum[mlp][tid + 32]);
#pragma unroll
        for (int o = 16; o; o >>= 1) s += __shfl_xor_sync(0xffffffffu, s, o);
        if (tid == 0) sys = s;
    }
    __syncthreads();

    // ---- W stream: q-th row-quarter (32 rows), col cbase + (tid&31) ----
    const int q = tid >> 5;           // 0..3
    const int c = tid & 31;
    const float4* __restrict__ W4 =
        (const float4*)W + (size_t)(hbase + q * 32) * (RR / 4) + cbase + c;
    float4 A = make_float4(0.f, 0.f, 0.f, 0.f);
#pragma unroll
    for (int b = 0; b < 4; b++) {
        float4 w[8];
#pragma unroll
        for (int u = 0; u < 8; u++)
            w[u] = ldg4(W4 + (size_t)(b * 8 + u) * (RR / 4));
#pragma unroll
        for (int u = 0; u < 8; u++) {
            float th = t[q * 32 + b * 8 + u];
            A.x = fmaf(th, w[u].x, A.x);
            A.y = fmaf(th, w[u].y, A.y);
            A.z = fmaf(th, w[u].z, A.z);
            A.w = fmaf(th, w[u].w, A.w);
        }
    }
    tp[q][c] = A;
    __syncthreads();
    if (tid < 32) {
        float4 a0 = tp[0][tid], a1 = tp[1][tid], a2 = tp[2][tid], a3 = tp[3][tid];
        float4 r = make_float4((a0.x + a1.x) + (a2.x + a3.x),
                               (a0.y + a1.y) + (a2.y + a3.y),
                               (a0.z + a1.z) + (a2.z + a3.z),
                               (a0.w + a1.w) + (a2.w + a3.w));
        if (hc == 0) {
            float ys = sys;
            float4 b4 = ldg4((const float4*)B + cbase + tid);
            r.x = fmaf(ys, b4.x, r.x); r.y = fmaf(ys, b4.y, r.y);
            r.z = fmaf(ys, b4.z, r.z); r.w = fmaf(ys, b4.w, r.w);
        }
        ((float4*)&g_Spart[mlp][hc][0])[cbase + tid] = r;
    }
    cudaTriggerProgrammaticLaunchCompletion();
}

// ---------------------------------------------------------------------------
// K3: reduce 8 Spart partials (forced staging batch) -> padded smem S0/S1,
// then r[b*64+d] = sum_x S0[b,x]*S1[d,x]; per-block cpart = bx2-dot partial.
// grid: 16 blocks x 256 threads (4 b-rows per block).
// ---------------------------------------------------------------------------
__global__ void __launch_bounds__(256)
k3_rhs(const float* __restrict__ bx2)
{
    cudaGridDependencySynchronize();

    __shared__ float s1[64 * 65];
    __shared__ float s0[4 * 65];
    __shared__ float p8[8];
    const int tid = threadIdx.x;   // 0..255
    const int bbase = blockIdx.x * 4;

    const float4* __restrict__ base1 = (const float4*)g_Spart + (size_t)NHC * (RR / 4);
    const float4* __restrict__ base0 = (const float4*)g_Spart;

    // forced batches: S1 = 4 cols x 8 partials; S0 = 8 partials (tid<64)
    float4 vv[32];
#pragma unroll
    for (int k = 0; k < 4; k++)
#pragma unroll
        for (int p = 0; p < 8; p++)
            vv[k * 8 + p] = ldg4(base1 + (size_t)p * (RR / 4) + k * 256 + tid);
    float4 w0 = make_float4(0.f, 0.f, 0.f, 0.f);
    if (tid < 64) {
        float4 u[8];
#pragma unroll
        for (int p = 0; p < 8; p++)
            u[p] = ldg4(base0 + (size_t)p * (RR / 4) + bbase * 16 + tid);
#pragma unroll
        for (int p = 0; p < 8; p++) {
            w0.x += u[p].x; w0.y += u[p].y; w0.z += u[p].z; w0.w += u[p].w;
        }
    }

#pragma unroll
    for (int k = 0; k < 4; k++) {
        float4 a = make_float4(0.f, 0.f, 0.f, 0.f);
#pragma unroll
        for (int p = 0; p < 8; p++) {
            a.x += vv[k * 8 + p].x; a.y += vv[k * 8 + p].y;
            a.z += vv[k * 8 + p].z; a.w += vv[k * 8 + p].w;
        }
        int j4 = k * 256 + tid;
        float* dst = s1 + (j4 >> 4) * 65 + (j4 & 15) * 4;
        dst[0] = a.x; dst[1] = a.y; dst[2] = a.z; dst[3] = a.w;
    }
    if (tid < 64) {
        float* dst = s0 + (tid >> 4) * 65 + (tid & 15) * 4;
        dst[0] = w0.x; dst[1] = w0.y; dst[2] = w0.z; dst[3] = w0.w;
    }
    __syncthreads();

    const int b = tid >> 6;        // 0..3
    const int d = tid & 63;
    float acc = 0.0f;
#pragma unroll 16
    for (int x = 0; x < 64; x++)
        acc = fmaf(s0[b * 65 + x], s1[d * 65 + x], acc);
    const int o = (bbase + b) * 64 + d;
    g_r[o] = acc;

    float cacc = acc * ldgf(bx2 + o);
#pragma unroll
    for (int o2 = 16; o2; o2 >>= 1) cacc += __shfl_xor_sync(0xffffffffu, cacc, o2);
    if ((tid & 31) == 0) p8[tid >> 5] = cacc;
    __syncthreads();
    if (tid == 0) {
        float s = 0.0f;
#pragma unroll
        for (int i = 0; i < 8; i++) s += p8[i];
        g_cpart[blockIdx.x] = s;
    }
    cudaTriggerProgrammaticLaunchCompletion();
}

// ---------------------------------------------------------------------------
// K4: v[h] = Wx2[h,:] . r.  512 blocks x 256 threads, 2 rows per block.
// W batch preloaded BEFORE the dependency sync (overlaps k3's drain).
// Block 0 also finalizes c = sum(cpart).
// ---------------------------------------------------------------------------
__global__ void __launch_bounds__(256)
k4_v(const float* __restrict__ Wx2)
{
    const int tid = threadIdx.x;
    const int row = tid >> 7;                      // 0 or 1
    const int h = blockIdx.x * 2 + row;
    const int g = tid & 127;
    const float4* __restrict__ W4 = (const float4*)Wx2 + (size_t)h * (RR / 4) + g;

    float4 w[8];
#pragma unroll
    for (int k = 0; k < 8; k++)
        w[k] = ldg4(W4 + 128 * k);       // independent prologue (DRAM)

    cudaGridDependencySynchronize();

    if (blockIdx.x == 0 && tid == 0) {
        float s = 0.0f;
#pragma unroll
        for (int i = 0; i < 16; i++) s += ldcg(&g_cpart[i]);
        g_c = s;
    }

    float4 r[8];
#pragma unroll
    for (int k = 0; k < 8; k++)
        r[k] = ldg4((const float4*)g_r + g + 128 * k);
    float acc = 0.0f;
#pragma unroll
    for (int k = 0; k < 8; k++) {
        acc = fmaf(w[k].x, r[k].x, acc);
        acc = fmaf(w[k].y, r[k].y, acc);
        acc = fmaf(w[k].z, r[k].z, acc);
        acc = fmaf(w[k].w, r[k].w, acc);
    }
#pragma unroll
    for (int o = 16; o; o >>= 1) acc += __shfl_xor_sync(0xffffffffu, acc, o);
    __shared__ float part[8];
    if ((tid & 31) == 0) part[tid >> 5] = acc;
    __syncthreads();
    if (tid < 2)
        g_v[blockIdx.x * 2 + tid] = (part[4 * tid] + part[4 * tid + 1]) +
                                    (part[4 * tid + 2] + part[4 * tid + 3]);
    cudaTriggerProgrammaticLaunchCompletion();
}

// ---------------------------------------------------------------------------
// K5: out[n] = tanh(input[n] @ Wx1 + bx1) . v + c
// 512 blocks x 256 threads; Wx1/bx1 AND input staged BEFORE the sync.
// ---------------------------------------------------------------------------
__global__ void __launch_bounds__(256)
k5_out(const float* __restrict__ input, const float* __restrict__ Wx1,
       const float* __restrict__ bx1, float* __restrict__ out)
{
    __shared__ float4 swb[HID];   // (w0, w1, w2, bias)
    __shared__ float  sv[HID];
    const int tid = threadIdx.x;
    const int warp = tid >> 5, lane = tid & 31;
    const int nbase = (blockIdx.x * 8 + warp) * 4;

    float a0[4], a1[4], a2[4], a3[4], a4[4];
#pragma unroll
    for (int k = 0; k < 4; k++) {
        int h = tid + 256 * k;
        a0[k] = ldgf(Wx1 + h);
        a1[k] = ldgf(Wx1 + HID + h);
        a2[k] = ldgf(Wx1 + 2 * HID + h);
        a3[k] = ldgf(bx1 + h);
    }
    float x0[4], x1[4], x2[4];
#pragma unroll
    for (int nn = 0; nn < 4; nn++) {
        x0[nn] = ldgf(input + (nbase + nn) * 3 + 0);
        x1[nn] = ldgf(input + (nbase + nn) * 3 + 1);
        x2[nn] = ldgf(input + (nbase + nn) * 3 + 2);
    }

    cudaGridDependencySynchronize();

#pragma unroll
    for (int k = 0; k < 4; k++)
        a4[k] = ldcg(&g_v[tid + 256 * k]);
#pragma unroll
    for (int k = 0; k < 4; k++) {
        int h = tid + 256 * k;
        swb[h] = make_float4(a0[k], a1[k], a2[k], a3[k]);
        sv[h] = a4[k];
    }
    __syncthreads();

    const float c = ldcg(&g_c);
    float acc[4] = {0.0f, 0.0f, 0.0f, 0.0f};
#pragma unroll 4
    for (int k = 0; k < 32; k++) {
        int h = k * 32 + lane;
        float4 wb = swb[h];
        float vv = sv[h];
#pragma unroll
        for (int nn = 0; nn < 4; nn++) {
            float a = fmaf(x0[nn], wb.x, fmaf(x1[nn], wb.y, fmaf(x2[nn], wb.z, wb.w)));
            acc[nn] = fmaf(tanh_fast(a), vv, acc[nn]);
        }
    }
#pragma unroll
    for (int nn = 0; nn < 4; nn++) {
        float a = acc[nn];
#pragma unroll
        for (int o = 16; o; o >>= 1) a += __shfl_xor_sync(0xffffffffu, a, o);
        if (lane == 0) out[nbase + nn] = a + c;
    }
}

// ---------------------------------------------------------------------------
// Input order (metadata): 0 input, 1 eq_param, 2 quad_x0, 3 quad_x1,
// 4 Wx1, 5 bx1, 6 Wx2, 7 bx2, 8 Wq0a, 9 bq0a, 10 Wq0b, 11 bq0b,
// 12 Wq1a, 13 bq1a, 14 Wq1b, 15 bq1b
// ---------------------------------------------------------------------------
extern "C" void kernel_launch(void* const* d_in, const int* in_sizes, int n_in,
                              void* d_out, int out_size)
{
    const float* input  = (const float*)d_in[0];
    const float* eq     = (const float*)d_in[1];
    const float* qx0    = (const float*)d_in[2];
    const float* qx1    = (const float*)d_in[3];
    const float* Wx1    = (const float*)d_in[4];
    const float* bx1    = (const float*)d_in[5];
    const float* Wx2    = (const float*)d_in[6];
    const float* bx2    = (const float*)d_in[7];
    const float* Wq0a   = (const float*)d_in[8];
    const float* bq0a   = (const float*)d_in[9];
    const float* Wq0b   = (const float*)d_in[10];
    const float* bq0b   = (const float*)d_in[11];
    const float* Wq1a   = (const float*)d_in[12];
    const float* bq1a   = (const float*)d_in[13];
    const float* Wq1b   = (const float*)d_in[14];
    const float* bq1b   = (const float*)d_in[15];
    float* out = (float*)d_out;

    cudaLaunchAttribute attr[1];
    attr[0].id = cudaLaunchAttributeProgrammaticStreamSerialization;
    attr[0].val.programmaticStreamSerializationAllowed = 1;
    cudaLaunchConfig_t cfg = {};
    cfg.attrs = attr;
    cfg.numAttrs = 1;
    cfg.stream = 0;

    cfg.gridDim = dim3(128); cfg.blockDim = dim3(256);
    cudaError_t e = cudaLaunchKernelEx(&cfg, k1_quad, qx0, qx1, Wq0a, bq0a, Wq1a, bq1a, eq);
    if (e != cudaSuccess) {
        // PDL unavailable: plain serialized launches (grid-dep sync is a no-op)
        k1_quad<<<128, 256>>>(qx0, qx1, Wq0a, bq0a, Wq1a, bq1a, eq);
        k2_S<<<512, 128>>>(Wq0b, bq0b, Wq1b, bq1b);
        k3_rhs<<<16, 256>>>(bx2);
        k4_v<<<512, 256>>>(Wx2);
        k5_out<<<512, 256>>>(input, Wx1, bx1, out);
        return;
    }
    cfg.gridDim = dim3(512); cfg.blockDim = dim3(128);
    cudaLaunchKernelEx(&cfg, k2_S, Wq0b, bq0b, Wq1b, bq1b);
    cfg.gridDim = dim3(16); cfg.blockDim = dim3(256);
    cudaLaunchKernelEx(&cfg, k3_rhs, bx2);
    cfg.gridDim = dim3(512); cfg.blockDim = dim3(256);
    cudaLaunchKernelEx(&cfg, k4_v, Wx2);
    cfg.gridDim = dim3(512); cfg.blockDim = dim3(256);
    cudaLaunchKernelEx(&cfg, k5_out, input, Wx1, bx1, out);
}